// round 4
// baseline (speedup 1.0000x reference)
#include <cuda_runtime.h>
#include <math.h>

#define NN 10000   // nodes
#define NE 160000  // edges
#define NG 32      // graphs
#define HD 128     // hidden

// ---------------------------------------------------------------------------
// Static device scratch (allocation-free rule)
// ---------------------------------------------------------------------------
__device__ float g_h [NN * HD];        // node state h            [N,128]
__device__ float g_A [NN * 2 * HD];    // h@W1_top + b1 ; reused as agg  [N,256]
__device__ float g_B [NN * 2 * HD];    // h@W1_bot ; reused as relu(update) [N,256]
__device__ float g_T [NN * 2 * HD];    // segment-summed relu ; reused as nx [N,256]
__device__ float g_UI[NN * 3 * HD];    // concat(agg, h)          [N,384]
__device__ float g_dg[NN];             // per-node in-degree (float)
__device__ float g_gg[NG * HD];        // pooled per-graph        [32,128]

// ---------------------------------------------------------------------------
// Helpers for packed fp32x2 math (Blackwell FFMA2 — only reachable via PTX)
// ---------------------------------------------------------------------------
__device__ __forceinline__ unsigned long long pack2(float v) {
    unsigned long long r;
    unsigned u = __float_as_uint(v);
    asm("mov.b64 %0, {%1, %1};" : "=l"(r) : "r"(u));
    return r;
}

// ---------------------------------------------------------------------------
// SGEMM: C[M,N] = op(A[M,K] @ Bw[K,N] + bias)   (all row-major)
//   EPI = 0 : C = acc + bias             (bias may be scaled per-row by rowscale)
//   EPI = 1 : C = relu(acc + bias)
//   EPI = 2 : C = C + acc + bias         (residual accumulate)
// Requirements: N % 128 == 0 (grid.y = N/128), K % 16 == 0. M arbitrary.
// Tile: BM=64, BN=128, BK=16, 256 threads, TM=4, TN=8, accumulators packed
// in f32x2 pairs along M so the inner loop is pure fma.rn.f32x2.
// ---------------------------------------------------------------------------
template <int EPI>
__global__ __launch_bounds__(256)
void sgemm_kernel(const float* __restrict__ A, const float* __restrict__ Bw,
                  float* __restrict__ C, const float* __restrict__ bias,
                  const float* __restrict__ rowscale,
                  int M, int N, int K)
{
    constexpr int BM = 64, BN = 128, BK = 16, TM = 4, TN = 8, TM2 = TM / 2;

    __shared__ __align__(16) float As[BK][BM + 4];   // transposed A tile (padded)
    __shared__ __align__(16) float Bs[BK][BN];

    const int tid = threadIdx.x;
    const int tx = tid & 15;        // column group (TN=8 cols each)
    const int ty = tid >> 4;        // row group    (TM=4 rows each)
    const int m0 = blockIdx.x * BM;
    const int n0 = blockIdx.y * BN;

    // --- load index precompute -------------------------------------------
    // A tile: 64 rows x 16 cols = 256 float4 -> 1 per thread
    const int arow = tid >> 2;      // 0..63
    const int ac4  = tid & 3;       // 0..3  (float4 col within BK)
    // B tile: 16 rows x 128 cols = 512 float4 -> 2 per thread
    const int brow = tid >> 5;      // 0..7 (second load uses brow+8)
    const int bc4  = tid & 31;      // 0..31

    unsigned long long acc[TM2][TN];
#pragma unroll
    for (int i = 0; i < TM2; i++)
#pragma unroll
        for (int j = 0; j < TN; j++) acc[i][j] = 0ULL;

    float4 aReg, bReg0, bReg1;

    // prologue: load tile 0
    {
        const int gr = m0 + arow;
        aReg = (gr < M) ? *reinterpret_cast<const float4*>(A + (size_t)gr * K + ac4 * 4)
                        : make_float4(0.f, 0.f, 0.f, 0.f);
        bReg0 = *reinterpret_cast<const float4*>(Bw + (size_t)(brow)     * N + n0 + bc4 * 4);
        bReg1 = *reinterpret_cast<const float4*>(Bw + (size_t)(brow + 8) * N + n0 + bc4 * 4);
    }
    As[ac4 * 4 + 0][arow] = aReg.x;
    As[ac4 * 4 + 1][arow] = aReg.y;
    As[ac4 * 4 + 2][arow] = aReg.z;
    As[ac4 * 4 + 3][arow] = aReg.w;
    *reinterpret_cast<float4*>(&Bs[brow][bc4 * 4])     = bReg0;
    *reinterpret_cast<float4*>(&Bs[brow + 8][bc4 * 4]) = bReg1;
    __syncthreads();

    const int numTiles = K >> 4;
    for (int t = 0; t < numTiles; t++) {
        // prefetch next tile into registers while computing on smem
        if (t + 1 < numTiles) {
            const int k0 = (t + 1) << 4;
            const int gr = m0 + arow;
            aReg = (gr < M) ? *reinterpret_cast<const float4*>(A + (size_t)gr * K + k0 + ac4 * 4)
                            : make_float4(0.f, 0.f, 0.f, 0.f);
            bReg0 = *reinterpret_cast<const float4*>(Bw + (size_t)(k0 + brow)     * N + n0 + bc4 * 4);
            bReg1 = *reinterpret_cast<const float4*>(Bw + (size_t)(k0 + brow + 8) * N + n0 + bc4 * 4);
        }

#pragma unroll
        for (int k = 0; k < BK; k++) {
            // a pairs: rows (4ty+0,4ty+1) and (4ty+2,4ty+3) packed as f32x2
            const unsigned long long* Ap =
                reinterpret_cast<const unsigned long long*>(&As[k][ty * TM]);
            unsigned long long a0 = Ap[0];
            unsigned long long a1 = Ap[1];
            // b values: 8 cols, broadcast each into both f32x2 lanes
            float4 bq0 = *reinterpret_cast<const float4*>(&Bs[k][tx * TN]);
            float4 bq1 = *reinterpret_cast<const float4*>(&Bs[k][tx * TN + 4]);
            unsigned long long b2[TN];
            b2[0] = pack2(bq0.x); b2[1] = pack2(bq0.y);
            b2[2] = pack2(bq0.z); b2[3] = pack2(bq0.w);
            b2[4] = pack2(bq1.x); b2[5] = pack2(bq1.y);
            b2[6] = pack2(bq1.z); b2[7] = pack2(bq1.w);
#pragma unroll
            for (int j = 0; j < TN; j++) {
                asm("fma.rn.f32x2 %0, %1, %2, %0;" : "+l"(acc[0][j]) : "l"(a0), "l"(b2[j]));
                asm("fma.rn.f32x2 %0, %1, %2, %0;" : "+l"(acc[1][j]) : "l"(a1), "l"(b2[j]));
            }
        }
        __syncthreads();
        if (t + 1 < numTiles) {
            As[ac4 * 4 + 0][arow] = aReg.x;
            As[ac4 * 4 + 1][arow] = aReg.y;
            As[ac4 * 4 + 2][arow] = aReg.z;
            As[ac4 * 4 + 3][arow] = aReg.w;
            *reinterpret_cast<float4*>(&Bs[brow][bc4 * 4])     = bReg0;
            *reinterpret_cast<float4*>(&Bs[brow + 8][bc4 * 4]) = bReg1;
            __syncthreads();
        }
    }

    // epilogue
#pragma unroll
    for (int i = 0; i < TM2; i++) {
        const int r = m0 + ty * TM + 2 * i;
#pragma unroll
        for (int j = 0; j < TN; j++) {
            const int c = n0 + tx * TN + j;
            unsigned ulo, uhi;
            asm("mov.b64 {%0, %1}, %2;" : "=r"(ulo), "=r"(uhi) : "l"(acc[i][j]));
            const float lo = __uint_as_float(ulo);
            const float hi = __uint_as_float(uhi);
            const float bval = bias ? bias[c] : 0.0f;
            if (r < M) {
                float v = lo + (rowscale ? bval * rowscale[r] : bval);
                if (EPI == 1) v = fmaxf(v, 0.f);
                if (EPI == 2) v += C[(size_t)r * N + c];
                C[(size_t)r * N + c] = v;
            }
            if (r + 1 < M) {
                float v = hi + (rowscale ? bval * rowscale[r + 1] : bval);
                if (EPI == 1) v = fmaxf(v, 0.f);
                if (EPI == 2) v += C[(size_t)(r + 1) * N + c];
                C[(size_t)(r + 1) * N + c] = v;
            }
        }
    }
}

// ---------------------------------------------------------------------------
// Elementwise / graph kernels
// ---------------------------------------------------------------------------
__global__ void zero_kernel(float4* __restrict__ p, int n4) {
    int i = blockIdx.x * blockDim.x + threadIdx.x;
    if (i < n4) p[i] = make_float4(0.f, 0.f, 0.f, 0.f);
}

__global__ void deg_kernel(const int* __restrict__ ei, float* __restrict__ deg, int E) {
    int e = blockIdx.x * blockDim.x + threadIdx.x;
    if (e < E) atomicAdd(deg + ei[e], 1.0f);   // ei[e] = target
}

// Per edge: t = relu(A[src] + B[tgt]) (256 floats) ; T[tgt] += t.
// 64 threads per edge (one float4 each). sm_90+ 128-bit vector RED.
__global__ void edge_kernel(const int* __restrict__ ei, const float* __restrict__ A,
                            const float* __restrict__ B, float* __restrict__ T, int E) {
    int gid  = blockIdx.x * blockDim.x + threadIdx.x;
    int e    = gid >> 6;
    int lane = gid & 63;
    if (e >= E) return;
    int tgt = ei[e];
    int src = ei[E + e];
    float4 a = *(reinterpret_cast<const float4*>(A + (size_t)src * 256) + lane);
    float4 b = *(reinterpret_cast<const float4*>(B + (size_t)tgt * 256) + lane);
    float4 t;
    t.x = fmaxf(a.x + b.x, 0.f);
    t.y = fmaxf(a.y + b.y, 0.f);
    t.z = fmaxf(a.z + b.z, 0.f);
    t.w = fmaxf(a.w + b.w, 0.f);
    atomicAdd(reinterpret_cast<float4*>(T + (size_t)tgt * 256) + lane, t);
}

// ui = concat(agg[N,256], h[N,128]) -> [N,384], one float4 per thread
__global__ void concat_kernel(const float4* __restrict__ agg, const float4* __restrict__ h,
                              float4* __restrict__ ui) {
    int i = blockIdx.x * blockDim.x + threadIdx.x;
    if (i >= NN * 96) return;
    int node = i / 96;
    int q    = i - node * 96;
    ui[i] = (q < 64) ? agg[(size_t)node * 64 + q] : h[(size_t)node * 32 + (q - 64)];
}

// v = sigmoid(nx[:, :128]) * nx[:, 128:] ; gg[batch[n]] += v
__global__ void gatepool_kernel(const float* __restrict__ nx, const int* __restrict__ batch,
                                float* __restrict__ gg) {
    int i = blockIdx.x * blockDim.x + threadIdx.x;
    if (i >= NN * 32) return;
    int node = i >> 5;
    int c4   = i & 31;
    const float4* row = reinterpret_cast<const float4*>(nx + (size_t)node * 256);
    float4 g = row[c4];
    float4 v = row[32 + c4];
    float4 o;
    o.x = v.x / (1.f + expf(-g.x));
    o.y = v.y / (1.f + expf(-g.y));
    o.z = v.z / (1.f + expf(-g.z));
    o.w = v.w / (1.f + expf(-g.w));
    int b = batch[node];
    atomicAdd(reinterpret_cast<float4*>(gg + (size_t)b * HD) + c4, o);
}

// ---------------------------------------------------------------------------
// Host orchestration
// ---------------------------------------------------------------------------
extern "C" void kernel_launch(void* const* d_in, const int* in_sizes, int n_in,
                              void* d_out, int out_size)
{
    (void)in_sizes; (void)n_in; (void)out_size;

    const float* W_emb   = (const float*)d_in[6];
    const float* b_emb   = (const float*)d_in[7];
    const float* msg_W1  = (const float*)d_in[8];
    const float* msg_b1  = (const float*)d_in[9];
    const float* msg_W2  = (const float*)d_in[10];
    const float* msg_b2  = (const float*)d_in[11];
    const float* upd_W1  = (const float*)d_in[12];
    const float* upd_b1  = (const float*)d_in[13];
    const float* upd_W2  = (const float*)d_in[14];
    const float* upd_b2  = (const float*)d_in[15];
    const float* node_W  = (const float*)d_in[16];
    const float* node_b  = (const float*)d_in[17];
    const float* graph_W = (const float*)d_in[18];
    const float* graph_b = (const float*)d_in[19];

    void *ph, *pA, *pB, *pT, *pUI, *pdg, *pgg;
    cudaGetSymbolAddress(&ph,  g_h);
    cudaGetSymbolAddress(&pA,  g_A);
    cudaGetSymbolAddress(&pB,  g_B);
    cudaGetSymbolAddress(&pT,  g_T);
    cudaGetSymbolAddress(&pUI, g_UI);
    cudaGetSymbolAddress(&pdg, g_dg);
    cudaGetSymbolAddress(&pgg, g_gg);
    float* h   = (float*)ph;
    float* A   = (float*)pA;
    float* B   = (float*)pB;
    float* T   = (float*)pT;
    float* UI  = (float*)pUI;
    float* dg  = (float*)pdg;
    float* gg  = (float*)pgg;

    const int MT = (NN + 63) / 64;     // 157 row tiles
    const dim3 gN256(MT, 2);           // N = 256 GEMMs
    const dim3 gN128(MT, 1);           // N = 128 GEMMs

    for (int br = 0; br < 2; br++) {
        const float* x     = (const float*)d_in[br * 3 + 0];
        const int*   ei    = (const int*)  d_in[br * 3 + 1];
        const int*   batch = (const int*)  d_in[br * 3 + 2];
        float*       outp  = (float*)d_out + (size_t)br * NG * HD;

        // h = x @ W_emb + b_emb                     [N,128], K=64
        sgemm_kernel<0><<<gN128, 256>>>(x, W_emb, h, b_emb, nullptr, NN, HD, 64);

        // per-node in-degree (shared by both layers of this branch)
        zero_kernel<<<(NN / 4 + 255) / 256, 256>>>((float4*)dg, NN / 4);
        deg_kernel<<<(NE + 255) / 256, 256>>>(ei, dg, NE);

        for (int l = 0; l < 2; l++) {
            const float* Wm1 = msg_W1 + (size_t)l * 256 * 256;
            const float* bm1 = msg_b1 + (size_t)l * 256;
            const float* Wm2 = msg_W2 + (size_t)l * 256 * 256;
            const float* bm2 = msg_b2 + (size_t)l * 256;
            const float* Wu1 = upd_W1 + (size_t)l * 384 * 256;
            const float* bu1 = upd_b1 + (size_t)l * 256;
            const float* Wu2 = upd_W2 + (size_t)l * 256 * 128;
            const float* bu2 = upd_b2 + (size_t)l * 128;

            // A = h @ W1[:128,:] + b1 ; B = h @ W1[128:,:]     (node-level hoist)
            sgemm_kernel<0><<<gN256, 256>>>(h, Wm1,             A, bm1,     nullptr, NN, 256, 128);
            sgemm_kernel<0><<<gN256, 256>>>(h, Wm1 + 128 * 256, B, nullptr, nullptr, NN, 256, 128);

            // T[n] = sum_{e: tgt=n} relu(A[src] + B[tgt])
            zero_kernel<<<(NN * 64 + 255) / 256, 256>>>((float4*)T, NN * 64);
            edge_kernel<<<(NE * 64 + 255) / 256, 256>>>(ei, A, B, T, NE);

            // agg = T @ W2 + deg * b2      (second hoist past segment-sum) -> A
            sgemm_kernel<0><<<gN256, 256>>>(T, Wm2, A, bm2, dg, NN, 256, 256);

            // ui = [agg | h] ; u1 = relu(ui @ uW1 + ub1) -> B
            concat_kernel<<<(NN * 96 + 255) / 256, 256>>>((const float4*)A, (const float4*)h,
                                                          (float4*)UI);
            sgemm_kernel<1><<<gN256, 256>>>(UI, Wu1, B, bu1, nullptr, NN, 256, 384);

            // h += u1 @ uW2 + ub2          (residual epilogue)
            sgemm_kernel<2><<<gN128, 256>>>(B, Wu2, h, bu2, nullptr, NN, 128, 256);
        }

        // readout: nx = h @ node_W + node_b -> T ; gate+pool ; graph GEMM
        sgemm_kernel<0><<<gN256, 256>>>(h, node_W, T, node_b, nullptr, NN, 256, 128);
        zero_kernel<<<(NG * 32 + 255) / 256, 256>>>((float4*)gg, NG * 32);
        gatepool_kernel<<<(NN * 32 + 255) / 256, 256>>>(T, batch, gg);
        sgemm_kernel<0><<<dim3(1, 1), 256>>>(gg, graph_W, outp, graph_b, nullptr, NG, HD, HD);
    }
}

// round 5
// speedup vs baseline: 1.2241x; 1.2241x over previous
#include <cuda_runtime.h>
#include <math.h>

#define NN 10000   // nodes
#define NE 160000  // edges
#define NG 32      // graphs
#define HD 128     // hidden

typedef unsigned long long ull;

// ---------------------------------------------------------------------------
// Static device scratch (allocation-free rule)
// ---------------------------------------------------------------------------
__device__ float g_h [NN * HD];        // node state h                 [N,128]
__device__ float g_A [NN * 2 * HD];    // h@W1_top + b1 ; reused as agg [N,256]
__device__ float g_B [NN * 2 * HD];    // h@W1_bot ; reused as relu(update) [N,256]
__device__ float g_T [NN * 2 * HD];    // segment-summed relu ; reused as nx [N,256]
__device__ float g_dg[NN];             // per-node in-degree (float)
__device__ float g_gg[NG * HD];        // pooled per-graph             [32,128]

// ---------------------------------------------------------------------------
// SGEMM: C[M,N] = op(A[M,K] @ Bw[K,N] + bias)       (row-major)
//   EPI 0 : C = acc + bias (bias optionally scaled per-row by rowscale)
//   EPI 2 : C = C + acc + bias                      (residual accumulate)
//   EPI 3 : C = relu(C + acc + bias)                (split-K relu finish)
//
// TM = 8 -> BM = 128 (for N=256 GEMMs: 79x2 = 158 blocks, ~1 wave)
// TM = 4 -> BM = 64  (for N=128 GEMMs: 157 blocks)
// BN=128, BK=16, 256 threads, 8x8 (or 4x8) outputs per thread.
// A is stored DUPLICATED in smem ((a,a) pairs) so the inner loop is pure
// LDS.128 + fma.rn.f32x2 (FFMA2) with no register packing MOVs.
// Requires N % 128 == 0, K % 16 == 0. M arbitrary.
// ---------------------------------------------------------------------------
template <int EPI, int TM>
__global__ __launch_bounds__(256, 2)
void sgemm(const float* __restrict__ Ag, const float* __restrict__ Bg,
           float* __restrict__ C, const float* __restrict__ bias,
           const float* __restrict__ rowscale, int M, int N, int K)
{
    constexpr int BM = TM * 16, BN = 128, BK = 16, TN2 = 4;
    constexpr int ALD = (BM * 4) / 256;   // float4 A-loads per thread (2 or 1)

    __shared__ __align__(16) float As2[2][BK][2 * BM];  // duplicated A (transposed)
    __shared__ __align__(16) float Bs [2][BK][BN];

    const int tid = threadIdx.x;
    const int tx = tid & 15;          // 16 col groups x 8 cols (split 4+4)
    const int ty = tid >> 4;          // 16 row groups x TM rows
    const int m0 = blockIdx.x * BM;
    const int n0 = blockIdx.y * BN;

    const int brow = tid >> 5;        // B tile: 16x128 = 512 float4, 2/thread
    const int bc4  = tid & 31;

    ull acc[TM][TN2];
#pragma unroll
    for (int i = 0; i < TM; i++)
#pragma unroll
        for (int j = 0; j < TN2; j++) acc[i][j] = 0ULL;

    float4 aR[ALD], bR0, bR1;

    auto ldg = [&](int kt) {
#pragma unroll
        for (int i = 0; i < ALD; i++) {
            const int idx = tid + i * 256;
            const int r = idx >> 2, c4 = idx & 3;
            const int gr = m0 + r;
            aR[i] = (gr < M)
                ? *reinterpret_cast<const float4*>(Ag + (size_t)gr * K + kt * BK + c4 * 4)
                : make_float4(0.f, 0.f, 0.f, 0.f);
        }
        bR0 = *reinterpret_cast<const float4*>(Bg + (size_t)(kt * BK + brow)     * N + n0 + bc4 * 4);
        bR1 = *reinterpret_cast<const float4*>(Bg + (size_t)(kt * BK + brow + 8) * N + n0 + bc4 * 4);
    };
    auto sts = [&](int buf) {
#pragma unroll
        for (int i = 0; i < ALD; i++) {
            const int idx = tid + i * 256;
            const int r = idx >> 2, c4 = idx & 3;
            *reinterpret_cast<float2*>(&As2[buf][c4 * 4 + 0][2 * r]) = make_float2(aR[i].x, aR[i].x);
            *reinterpret_cast<float2*>(&As2[buf][c4 * 4 + 1][2 * r]) = make_float2(aR[i].y, aR[i].y);
            *reinterpret_cast<float2*>(&As2[buf][c4 * 4 + 2][2 * r]) = make_float2(aR[i].z, aR[i].z);
            *reinterpret_cast<float2*>(&As2[buf][c4 * 4 + 3][2 * r]) = make_float2(aR[i].w, aR[i].w);
        }
        *reinterpret_cast<float4*>(&Bs[buf][brow][bc4 * 4])     = bR0;
        *reinterpret_cast<float4*>(&Bs[buf][brow + 8][bc4 * 4]) = bR1;
    };

    ldg(0); sts(0); __syncthreads();

    const int nt = K >> 4;
    for (int t = 0; t < nt; t++) {
        const int buf = t & 1;
        if (t + 1 < nt) ldg(t + 1);           // prefetch, latency hidden by compute

#pragma unroll
        for (int k = 0; k < BK; k++) {
            ull a[TM];
            const ulonglong2* ap =
                reinterpret_cast<const ulonglong2*>(&As2[buf][k][ty * 2 * TM]);
#pragma unroll
            for (int q = 0; q < TM / 2; q++) {
                ulonglong2 v = ap[q];
                a[2 * q] = v.x; a[2 * q + 1] = v.y;
            }
            ull b[TN2];
            ulonglong2 b0 = *reinterpret_cast<const ulonglong2*>(&Bs[buf][k][tx * 4]);
            ulonglong2 b1 = *reinterpret_cast<const ulonglong2*>(&Bs[buf][k][64 + tx * 4]);
            b[0] = b0.x; b[1] = b0.y; b[2] = b1.x; b[3] = b1.y;
#pragma unroll
            for (int i = 0; i < TM; i++)
#pragma unroll
                for (int j = 0; j < TN2; j++)
                    asm("fma.rn.f32x2 %0, %1, %2, %0;"
                        : "+l"(acc[i][j]) : "l"(a[i]), "l"(b[j]));
        }

        if (t + 1 < nt) sts(buf ^ 1);
        __syncthreads();
    }

    // --- epilogue ----------------------------------------------------------
    float bv[8];
#pragma unroll
    for (int j = 0; j < 4; j++) {
        bv[j]     = bias ? bias[n0 + tx * 4 + j]      : 0.f;
        bv[4 + j] = bias ? bias[n0 + 64 + tx * 4 + j] : 0.f;
    }

#pragma unroll
    for (int i = 0; i < TM; i++) {
        const int r = m0 + ty * TM + i;
        if (r < M) {
            const float rs = rowscale ? rowscale[r] : 1.f;
            float w[8];
#pragma unroll
            for (int j = 0; j < 4; j++) {
                unsigned lo, hi;
                asm("mov.b64 {%0,%1}, %2;" : "=r"(lo), "=r"(hi) : "l"(acc[i][j]));
                w[2 * j]     = __uint_as_float(lo) + bv[2 * j]     * rs;
                w[2 * j + 1] = __uint_as_float(hi) + bv[2 * j + 1] * rs;
            }
            float* c0 = C + (size_t)r * N + n0 + tx * 4;
            float* c1 = c0 + 64;
            if (EPI >= 2) {
                float4 p0 = *reinterpret_cast<float4*>(c0);
                float4 p1 = *reinterpret_cast<float4*>(c1);
                w[0] += p0.x; w[1] += p0.y; w[2] += p0.z; w[3] += p0.w;
                w[4] += p1.x; w[5] += p1.y; w[6] += p1.z; w[7] += p1.w;
            }
            if (EPI == 3) {
#pragma unroll
                for (int j = 0; j < 8; j++) w[j] = fmaxf(w[j], 0.f);
            }
            *reinterpret_cast<float4*>(c0) = make_float4(w[0], w[1], w[2], w[3]);
            *reinterpret_cast<float4*>(c1) = make_float4(w[4], w[5], w[6], w[7]);
        }
    }
}

// ---------------------------------------------------------------------------
// Elementwise / graph kernels
// ---------------------------------------------------------------------------
__global__ void zero_kernel(float4* __restrict__ p, int n4) {
    int i = blockIdx.x * blockDim.x + threadIdx.x;
    if (i < n4) p[i] = make_float4(0.f, 0.f, 0.f, 0.f);
}

__global__ void deg_kernel(const int* __restrict__ ei, float* __restrict__ deg, int E) {
    int e = blockIdx.x * blockDim.x + threadIdx.x;
    if (e < E) atomicAdd(deg + ei[e], 1.0f);   // ei[e] = target
}

// Per edge: t = relu(A[src] + B[tgt]) (256 floats) ; T[tgt] += t.
// 64 threads per edge (one float4 each). sm_90+ 128-bit vector RED.
__global__ void edge_kernel(const int* __restrict__ ei, const float* __restrict__ A,
                            const float* __restrict__ B, float* __restrict__ T, int E) {
    int gid  = blockIdx.x * blockDim.x + threadIdx.x;
    int e    = gid >> 6;
    int lane = gid & 63;
    if (e >= E) return;
    int tgt = ei[e];
    int src = ei[E + e];
    float4 a = *(reinterpret_cast<const float4*>(A + (size_t)src * 256) + lane);
    float4 b = *(reinterpret_cast<const float4*>(B + (size_t)tgt * 256) + lane);
    float4 t;
    t.x = fmaxf(a.x + b.x, 0.f);
    t.y = fmaxf(a.y + b.y, 0.f);
    t.z = fmaxf(a.z + b.z, 0.f);
    t.w = fmaxf(a.w + b.w, 0.f);
    atomicAdd(reinterpret_cast<float4*>(T + (size_t)tgt * 256) + lane, t);
}

// v = sigmoid(nx[:, :128]) * nx[:, 128:] ; gg[batch[n]] += v
__global__ void gatepool_kernel(const float* __restrict__ nx, const int* __restrict__ batch,
                                float* __restrict__ gg) {
    int i = blockIdx.x * blockDim.x + threadIdx.x;
    if (i >= NN * 32) return;
    int node = i >> 5;
    int c4   = i & 31;
    const float4* row = reinterpret_cast<const float4*>(nx + (size_t)node * 256);
    float4 g = row[c4];
    float4 v = row[32 + c4];
    float4 o;
    o.x = v.x / (1.f + expf(-g.x));
    o.y = v.y / (1.f + expf(-g.y));
    o.z = v.z / (1.f + expf(-g.z));
    o.w = v.w / (1.f + expf(-g.w));
    int b = batch[node];
    atomicAdd(reinterpret_cast<float4*>(gg + (size_t)b * HD) + c4, o);
}

// ---------------------------------------------------------------------------
// Host orchestration
// ---------------------------------------------------------------------------
extern "C" void kernel_launch(void* const* d_in, const int* in_sizes, int n_in,
                              void* d_out, int out_size)
{
    (void)in_sizes; (void)n_in; (void)out_size;

    const float* W_emb   = (const float*)d_in[6];
    const float* b_emb   = (const float*)d_in[7];
    const float* msg_W1  = (const float*)d_in[8];
    const float* msg_b1  = (const float*)d_in[9];
    const float* msg_W2  = (const float*)d_in[10];
    const float* msg_b2  = (const float*)d_in[11];
    const float* upd_W1  = (const float*)d_in[12];
    const float* upd_b1  = (const float*)d_in[13];
    const float* upd_W2  = (const float*)d_in[14];
    const float* upd_b2  = (const float*)d_in[15];
    const float* node_W  = (const float*)d_in[16];
    const float* node_b  = (const float*)d_in[17];
    const float* graph_W = (const float*)d_in[18];
    const float* graph_b = (const float*)d_in[19];

    void *ph, *pA, *pB, *pT, *pdg, *pgg;
    cudaGetSymbolAddress(&ph,  g_h);
    cudaGetSymbolAddress(&pA,  g_A);
    cudaGetSymbolAddress(&pB,  g_B);
    cudaGetSymbolAddress(&pT,  g_T);
    cudaGetSymbolAddress(&pdg, g_dg);
    cudaGetSymbolAddress(&pgg, g_gg);
    float* h  = (float*)ph;
    float* A  = (float*)pA;
    float* B  = (float*)pB;
    float* T  = (float*)pT;
    float* dg = (float*)pdg;
    float* gg = (float*)pgg;

    const int MT128 = (NN + 127) / 128;   // 79
    const int MT64  = (NN + 63) / 64;     // 157
    const dim3 gBig (MT128, 2);           // BM=128, N=256
    const dim3 gMed (MT64, 1);            // BM=64,  N=128

    for (int br = 0; br < 2; br++) {
        const float* x     = (const float*)d_in[br * 3 + 0];
        const int*   ei    = (const int*)  d_in[br * 3 + 1];
        const int*   batch = (const int*)  d_in[br * 3 + 2];
        float*       outp  = (float*)d_out + (size_t)br * NG * HD;

        // h = x @ W_emb + b_emb                       [N,128], K=64
        sgemm<0, 4><<<gMed, 256>>>(x, W_emb, h, b_emb, nullptr, NN, HD, 64);

        // per-node in-degree (shared by both layers of this branch)
        zero_kernel<<<(NN / 4 + 255) / 256, 256>>>((float4*)dg, NN / 4);
        deg_kernel<<<(NE + 255) / 256, 256>>>(ei, dg, NE);

        for (int l = 0; l < 2; l++) {
            const float* Wm1 = msg_W1 + (size_t)l * 256 * 256;
            const float* bm1 = msg_b1 + (size_t)l * 256;
            const float* Wm2 = msg_W2 + (size_t)l * 256 * 256;
            const float* bm2 = msg_b2 + (size_t)l * 256;
            const float* Wu1 = upd_W1 + (size_t)l * 384 * 256;
            const float* bu1 = upd_b1 + (size_t)l * 256;
            const float* Wu2 = upd_W2 + (size_t)l * 256 * 128;
            const float* bu2 = upd_b2 + (size_t)l * 128;

            // A = h @ W1[:128,:] + b1 ; B = h @ W1[128:,:]   (node-level hoist)
            sgemm<0, 8><<<gBig, 256>>>(h, Wm1,             A, bm1,     nullptr, NN, 256, 128);
            sgemm<0, 8><<<gBig, 256>>>(h, Wm1 + 128 * 256, B, nullptr, nullptr, NN, 256, 128);

            // T[n] = sum_{e: tgt=n} relu(A[src] + B[tgt])
            zero_kernel<<<(NN * 64 + 255) / 256, 256>>>((float4*)T, NN * 64);
            edge_kernel<<<(NE * 64 + 255) / 256, 256>>>(ei, A, B, T, NE);

            // agg = T @ W2 + deg * b2   (second hoist past segment-sum) -> A
            sgemm<0, 8><<<gBig, 256>>>(T, Wm2, A, bm2, dg, NN, 256, 256);

            // u1 = relu(agg @ Wu1[:256] + h @ Wu1[256:] + bu1)   (concat fused away)
            sgemm<0, 8><<<gBig, 256>>>(A, Wu1,             B, bu1,     nullptr, NN, 256, 256);
            sgemm<3, 8><<<gBig, 256>>>(h, Wu1 + 256 * 256, B, nullptr, nullptr, NN, 256, 128);

            // h += u1 @ uW2 + ub2       (residual epilogue)
            sgemm<2, 4><<<gMed, 256>>>(B, Wu2, h, bu2, nullptr, NN, 128, 256);
        }

        // readout: nx = h @ node_W + node_b -> T ; gate+pool ; graph GEMM
        sgemm<0, 8><<<gBig, 256>>>(h, node_W, T, node_b, nullptr, NN, 256, 128);
        zero_kernel<<<(NG * 32 + 255) / 256, 256>>>((float4*)gg, NG * 32);
        gatepool_kernel<<<(NN * 32 + 255) / 256, 256>>>(T, batch, gg);
        sgemm<0, 4><<<dim3(1, 1), 256>>>(gg, graph_W, outp, graph_b, nullptr, NG, HD, HD);
    }
}

// round 6
// speedup vs baseline: 1.5710x; 1.2834x over previous
#include <cuda_runtime.h>
#include <math.h>

#define NN 10000   // nodes per branch
#define NE 160000  // edges per branch
#define NG 32      // graphs per branch
#define HD 128     // hidden
#define NB (2*NN)  // stacked nodes (both branches)

typedef unsigned long long ull;

// ---------------------------------------------------------------------------
// Static device scratch (allocation-free rule). Both branches stacked.
// ---------------------------------------------------------------------------
__device__ float g_h [NB * HD];        // node state h                 [2N,128]
__device__ float g_A [NB * 2 * HD];    // h@W1_top + b1 ; reused as agg [2N,256]
__device__ float g_B [NB * 2 * HD];    // h@W1_bot ; reused as relu(update)
__device__ float g_T [NB * 2 * HD];    // segment-summed relu ; reused as nx
__device__ float g_dg[NB];             // per-node in-degree (float)
__device__ float g_gg[2 * NG * HD];    // pooled per-graph             [64,128]

// ---------------------------------------------------------------------------
// SGEMM: C[M,N] = op(A[M,K] @ Bw[K,N] + bias)       (row-major)
//   EPI 0 : C = acc + bias (bias optionally scaled per-row by rowscale)
//   EPI 2 : C = C + acc + bias                      (residual accumulate)
//   EPI 3 : C = relu(C + acc + bias)                (split-K relu finish)
// TM=8 -> BM=128 ; TM=4 -> BM=64. BN=128, BK=16, 256 threads.
// A duplicated in smem ((a,a) pairs) so the inner loop is pure
// LDS.128 + fma.rn.f32x2 (FFMA2). N % 128 == 0, K % 16 == 0.
// ---------------------------------------------------------------------------
template <int EPI, int TM>
__global__ __launch_bounds__(256, 2)
void sgemm(const float* __restrict__ Ag, const float* __restrict__ Bg,
           float* __restrict__ C, const float* __restrict__ bias,
           const float* __restrict__ rowscale, int M, int N, int K)
{
    constexpr int BM = TM * 16, BN = 128, BK = 16, TN2 = 4;
    constexpr int ALD = (BM * 4) / 256;   // float4 A-loads per thread (2 or 1)

    __shared__ __align__(16) float As2[2][BK][2 * BM];  // duplicated A (transposed)
    __shared__ __align__(16) float Bs [2][BK][BN];

    const int tid = threadIdx.x;
    const int tx = tid & 15;
    const int ty = tid >> 4;
    const int m0 = blockIdx.x * BM;
    const int n0 = blockIdx.y * BN;

    const int brow = tid >> 5;
    const int bc4  = tid & 31;

    ull acc[TM][TN2];
#pragma unroll
    for (int i = 0; i < TM; i++)
#pragma unroll
        for (int j = 0; j < TN2; j++) acc[i][j] = 0ULL;

    float4 aR[ALD], bR0, bR1;

    auto ldg = [&](int kt) {
#pragma unroll
        for (int i = 0; i < ALD; i++) {
            const int idx = tid + i * 256;
            const int r = idx >> 2, c4 = idx & 3;
            const int gr = m0 + r;
            aR[i] = (gr < M)
                ? *reinterpret_cast<const float4*>(Ag + (size_t)gr * K + kt * BK + c4 * 4)
                : make_float4(0.f, 0.f, 0.f, 0.f);
        }
        bR0 = *reinterpret_cast<const float4*>(Bg + (size_t)(kt * BK + brow)     * N + n0 + bc4 * 4);
        bR1 = *reinterpret_cast<const float4*>(Bg + (size_t)(kt * BK + brow + 8) * N + n0 + bc4 * 4);
    };
    auto sts = [&](int buf) {
#pragma unroll
        for (int i = 0; i < ALD; i++) {
            const int idx = tid + i * 256;
            const int r = idx >> 2, c4 = idx & 3;
            *reinterpret_cast<float2*>(&As2[buf][c4 * 4 + 0][2 * r]) = make_float2(aR[i].x, aR[i].x);
            *reinterpret_cast<float2*>(&As2[buf][c4 * 4 + 1][2 * r]) = make_float2(aR[i].y, aR[i].y);
            *reinterpret_cast<float2*>(&As2[buf][c4 * 4 + 2][2 * r]) = make_float2(aR[i].z, aR[i].z);
            *reinterpret_cast<float2*>(&As2[buf][c4 * 4 + 3][2 * r]) = make_float2(aR[i].w, aR[i].w);
        }
        *reinterpret_cast<float4*>(&Bs[buf][brow][bc4 * 4])     = bR0;
        *reinterpret_cast<float4*>(&Bs[buf][brow + 8][bc4 * 4]) = bR1;
    };

    ldg(0); sts(0); __syncthreads();

    const int nt = K >> 4;
    for (int t = 0; t < nt; t++) {
        const int buf = t & 1;
        if (t + 1 < nt) ldg(t + 1);           // prefetch, hidden under compute

#pragma unroll
        for (int k = 0; k < BK; k++) {
            ull a[TM];
            const ulonglong2* ap =
                reinterpret_cast<const ulonglong2*>(&As2[buf][k][ty * 2 * TM]);
#pragma unroll
            for (int q = 0; q < TM / 2; q++) {
                ulonglong2 v = ap[q];
                a[2 * q] = v.x; a[2 * q + 1] = v.y;
            }
            ull b[TN2];
            ulonglong2 b0 = *reinterpret_cast<const ulonglong2*>(&Bs[buf][k][tx * 4]);
            ulonglong2 b1 = *reinterpret_cast<const ulonglong2*>(&Bs[buf][k][64 + tx * 4]);
            b[0] = b0.x; b[1] = b0.y; b[2] = b1.x; b[3] = b1.y;
#pragma unroll
            for (int i = 0; i < TM; i++)
#pragma unroll
                for (int j = 0; j < TN2; j++)
                    asm("fma.rn.f32x2 %0, %1, %2, %0;"
                        : "+l"(acc[i][j]) : "l"(a[i]), "l"(b[j]));
        }

        if (t + 1 < nt) sts(buf ^ 1);
        __syncthreads();
    }

    // --- epilogue ----------------------------------------------------------
    float bv[8];
#pragma unroll
    for (int j = 0; j < 4; j++) {
        bv[j]     = bias ? bias[n0 + tx * 4 + j]      : 0.f;
        bv[4 + j] = bias ? bias[n0 + 64 + tx * 4 + j] : 0.f;
    }

#pragma unroll
    for (int i = 0; i < TM; i++) {
        const int r = m0 + ty * TM + i;
        if (r < M) {
            const float rs = rowscale ? rowscale[r] : 1.f;
            float w[8];
#pragma unroll
            for (int j = 0; j < 4; j++) {
                unsigned lo, hi;
                asm("mov.b64 {%0,%1}, %2;" : "=r"(lo), "=r"(hi) : "l"(acc[i][j]));
                w[2 * j]     = __uint_as_float(lo) + bv[2 * j]     * rs;
                w[2 * j + 1] = __uint_as_float(hi) + bv[2 * j + 1] * rs;
            }
            float* c0 = C + (size_t)r * N + n0 + tx * 4;
            float* c1 = c0 + 64;
            if (EPI >= 2) {
                float4 p0 = *reinterpret_cast<float4*>(c0);
                float4 p1 = *reinterpret_cast<float4*>(c1);
                w[0] += p0.x; w[1] += p0.y; w[2] += p0.z; w[3] += p0.w;
                w[4] += p1.x; w[5] += p1.y; w[6] += p1.z; w[7] += p1.w;
            }
            if (EPI == 3) {
#pragma unroll
                for (int j = 0; j < 8; j++) w[j] = fmaxf(w[j], 0.f);
            }
            *reinterpret_cast<float4*>(c0) = make_float4(w[0], w[1], w[2], w[3]);
            *reinterpret_cast<float4*>(c1) = make_float4(w[4], w[5], w[6], w[7]);
        }
    }
}

// ---------------------------------------------------------------------------
// Elementwise / graph kernels (both branches fused)
// ---------------------------------------------------------------------------
__global__ void zero_kernel(float4* __restrict__ p, int n4) {
    int i = blockIdx.x * blockDim.x + threadIdx.x;
    if (i < n4) p[i] = make_float4(0.f, 0.f, 0.f, 0.f);
}

__global__ void deg_kernel(const int* __restrict__ ei1, const int* __restrict__ ei2,
                           float* __restrict__ deg) {
    int e = blockIdx.x * blockDim.x + threadIdx.x;
    if (e >= 2 * NE) return;
    int t = (e < NE) ? ei1[e] : (ei2[e - NE] + NN);
    atomicAdd(deg + t, 1.0f);
}

// Per edge: t = relu(A[src] + B[tgt]) (256 floats) ; T[tgt] += t.
// 64 threads per edge (one float4 each). Both branches in one grid.
__global__ void edge_kernel(const int* __restrict__ ei1, const int* __restrict__ ei2,
                            const float* __restrict__ A, const float* __restrict__ B,
                            float* __restrict__ T) {
    long long gid = (long long)blockIdx.x * blockDim.x + threadIdx.x;
    int e    = (int)(gid >> 6);
    int lane = (int)(gid & 63);
    if (e >= 2 * NE) return;
    int tgt, src;
    if (e < NE) { tgt = ei1[e];      src = ei1[NE + e]; }
    else        { e -= NE; tgt = ei2[e] + NN; src = ei2[NE + e] + NN; }
    float4 a = *(reinterpret_cast<const float4*>(A + (size_t)src * 256) + lane);
    float4 b = *(reinterpret_cast<const float4*>(B + (size_t)tgt * 256) + lane);
    float4 t;
    t.x = fmaxf(a.x + b.x, 0.f);
    t.y = fmaxf(a.y + b.y, 0.f);
    t.z = fmaxf(a.z + b.z, 0.f);
    t.w = fmaxf(a.w + b.w, 0.f);
    atomicAdd(reinterpret_cast<float4*>(T + (size_t)tgt * 256) + lane, t);
}

// v = sigmoid(nx[:, :128]) * nx[:, 128:] ; gg[graph(node)] += v
__global__ void gatepool_kernel(const float* __restrict__ nx,
                                const int* __restrict__ batch1,
                                const int* __restrict__ batch2,
                                float* __restrict__ gg) {
    int i = blockIdx.x * blockDim.x + threadIdx.x;
    if (i >= NB * 32) return;
    int node = i >> 5;
    int c4   = i & 31;
    const float4* row = reinterpret_cast<const float4*>(nx + (size_t)node * 256);
    float4 g = row[c4];
    float4 v = row[32 + c4];
    float4 o;
    o.x = v.x / (1.f + expf(-g.x));
    o.y = v.y / (1.f + expf(-g.y));
    o.z = v.z / (1.f + expf(-g.z));
    o.w = v.w / (1.f + expf(-g.w));
    int b = (node < NN) ? batch1[node] : (batch2[node - NN] + NG);
    atomicAdd(reinterpret_cast<float4*>(gg + (size_t)b * HD) + c4, o);
}

// ---------------------------------------------------------------------------
// Host orchestration — both branches stacked (M = 20000 GEMMs, shared weights)
// ---------------------------------------------------------------------------
extern "C" void kernel_launch(void* const* d_in, const int* in_sizes, int n_in,
                              void* d_out, int out_size)
{
    (void)in_sizes; (void)n_in; (void)out_size;

    const float* x1      = (const float*)d_in[0];
    const int*   ei1     = (const int*)  d_in[1];
    const int*   batch1  = (const int*)  d_in[2];
    const float* x2      = (const float*)d_in[3];
    const int*   ei2     = (const int*)  d_in[4];
    const int*   batch2  = (const int*)  d_in[5];
    const float* W_emb   = (const float*)d_in[6];
    const float* b_emb   = (const float*)d_in[7];
    const float* msg_W1  = (const float*)d_in[8];
    const float* msg_b1  = (const float*)d_in[9];
    const float* msg_W2  = (const float*)d_in[10];
    const float* msg_b2  = (const float*)d_in[11];
    const float* upd_W1  = (const float*)d_in[12];
    const float* upd_b1  = (const float*)d_in[13];
    const float* upd_W2  = (const float*)d_in[14];
    const float* upd_b2  = (const float*)d_in[15];
    const float* node_W  = (const float*)d_in[16];
    const float* node_b  = (const float*)d_in[17];
    const float* graph_W = (const float*)d_in[18];
    const float* graph_b = (const float*)d_in[19];

    void *ph, *pA, *pB, *pT, *pdg, *pgg;
    cudaGetSymbolAddress(&ph,  g_h);
    cudaGetSymbolAddress(&pA,  g_A);
    cudaGetSymbolAddress(&pB,  g_B);
    cudaGetSymbolAddress(&pT,  g_T);
    cudaGetSymbolAddress(&pdg, g_dg);
    cudaGetSymbolAddress(&pgg, g_gg);
    float* h  = (float*)ph;
    float* A  = (float*)pA;
    float* B  = (float*)pB;
    float* T  = (float*)pT;
    float* dg = (float*)pdg;
    float* gg = (float*)pgg;

    const dim3 gBig ((NB + 127) / 128, 2);   // BM=128, N=256 -> 314 blocks
    const dim3 gMed ((NB + 63) / 64, 1);     // BM=64,  N=128 -> 313 blocks
    const dim3 gEmb ((NN + 63) / 64, 1);     // per-branch embedding

    // h = x @ W_emb + b_emb  (two source buffers, stacked destination)
    sgemm<0, 4><<<gEmb, 256>>>(x1, W_emb, h,            b_emb, nullptr, NN, HD, 64);
    sgemm<0, 4><<<gEmb, 256>>>(x2, W_emb, h + (size_t)NN * HD, b_emb, nullptr, NN, HD, 64);

    // per-node in-degree (both branches)
    zero_kernel<<<(NB / 4 + 255) / 256, 256>>>((float4*)dg, NB / 4);
    deg_kernel<<<(2 * NE + 255) / 256, 256>>>(ei1, ei2, dg);

    for (int l = 0; l < 2; l++) {
        const float* Wm1 = msg_W1 + (size_t)l * 256 * 256;
        const float* bm1 = msg_b1 + (size_t)l * 256;
        const float* Wm2 = msg_W2 + (size_t)l * 256 * 256;
        const float* bm2 = msg_b2 + (size_t)l * 256;
        const float* Wu1 = upd_W1 + (size_t)l * 384 * 256;
        const float* bu1 = upd_b1 + (size_t)l * 256;
        const float* Wu2 = upd_W2 + (size_t)l * 256 * 128;
        const float* bu2 = upd_b2 + (size_t)l * 128;

        // A = h @ W1[:128,:] + b1 ; B = h @ W1[128:,:]   (node-level hoist)
        sgemm<0, 8><<<gBig, 256>>>(h, Wm1,             A, bm1,     nullptr, NB, 256, 128);
        sgemm<0, 8><<<gBig, 256>>>(h, Wm1 + 128 * 256, B, nullptr, nullptr, NB, 256, 128);

        // T[n] = sum_{e: tgt=n} relu(A[src] + B[tgt])
        zero_kernel<<<(NB * 64 + 255) / 256, 256>>>((float4*)T, NB * 64);
        edge_kernel<<<(2 * NE * 64 + 255) / 256, 256>>>(ei1, ei2, A, B, T);

        // agg = T @ W2 + deg * b2   (hoist past segment-sum) -> A
        sgemm<0, 8><<<gBig, 256>>>(T, Wm2, A, bm2, dg, NB, 256, 256);

        // u1 = relu(agg @ Wu1[:256] + h @ Wu1[256:] + bu1)   (concat fused away)
        sgemm<0, 8><<<gBig, 256>>>(A, Wu1,             B, bu1,     nullptr, NB, 256, 256);
        sgemm<3, 8><<<gBig, 256>>>(h, Wu1 + 256 * 256, B, nullptr, nullptr, NB, 256, 128);

        // h += u1 @ uW2 + ub2       (residual epilogue)
        sgemm<2, 4><<<gMed, 256>>>(B, Wu2, h, bu2, nullptr, NB, 128, 256);
    }

    // readout: nx = h @ node_W + node_b -> T ; gate+pool ; graph GEMM
    sgemm<0, 8><<<gBig, 256>>>(h, node_W, T, node_b, nullptr, NB, 256, 128);
    zero_kernel<<<(2 * NG * 32 + 255) / 256, 256>>>((float4*)gg, 2 * NG * 32);
    gatepool_kernel<<<(NB * 32 + 255) / 256, 256>>>(T, batch1, batch2, gg);
    // out[2,32,128] contiguous = [64,128]
    sgemm<0, 4><<<dim3(1, 1), 256>>>(gg, graph_W, (float*)d_out, graph_b, nullptr,
                                     2 * NG, HD, HD);
}

// round 7
// speedup vs baseline: 1.5742x; 1.0020x over previous
#include <cuda_runtime.h>
#include <math.h>

#define NN 10000   // nodes per branch
#define NE 160000  // edges per branch
#define NG 32      // graphs per branch
#define HD 128     // hidden
#define NB (2*NN)  // stacked nodes (both branches)

typedef unsigned long long ull;

// ---------------------------------------------------------------------------
// Static device scratch (allocation-free rule). Both branches stacked.
// ---------------------------------------------------------------------------
__device__ float g_h [NB * HD];        // node state h                 [2N,128]
__device__ float g_A [NB * 2 * HD];    // h@W1_top + b1 ; reused as agg [2N,256]
__device__ float g_B [NB * 2 * HD];    // h@W1_bot ; reused as relu(update)
__device__ float g_T [NB * 2 * HD];    // segment-summed relu ; reused as nx
__device__ float g_dg[NB];             // per-node in-degree (float)
__device__ float g_gg[2 * NG * HD];    // pooled per-graph             [64,128]

// ---------------------------------------------------------------------------
// SGEMM: C[M,N] = op(A[M,K] @ Bw[K,N] + bias)       (row-major)
//   EPI 0 : C = acc + bias (bias optionally scaled per-row by rowscale)
//   EPI 2 : C = C + acc + bias                      (residual accumulate)
//   EPI 3 : C = relu(C + acc + bias)                (split-K relu finish)
// TM=8 -> BM=128 ; TM=4 -> BM=64. BN=128, BK=16, 256 threads.
// A duplicated in smem ((a,a) pairs) so the inner loop is pure
// LDS.128 + fma.rn.f32x2 (FFMA2). N % 128 == 0, K % 16 == 0.
// ---------------------------------------------------------------------------
template <int EPI, int TM>
__global__ __launch_bounds__(256, 2)
void sgemm(const float* __restrict__ Ag, const float* __restrict__ Bg,
           float* __restrict__ C, const float* __restrict__ bias,
           const float* __restrict__ rowscale, int M, int N, int K)
{
    constexpr int BM = TM * 16, BN = 128, BK = 16, TN2 = 4;
    constexpr int ALD = (BM * 4) / 256;   // float4 A-loads per thread (2 or 1)

    __shared__ __align__(16) float As2[2][BK][2 * BM];  // duplicated A (transposed)
    __shared__ __align__(16) float Bs [2][BK][BN];

    const int tid = threadIdx.x;
    const int tx = tid & 15;
    const int ty = tid >> 4;
    const int m0 = blockIdx.x * BM;
    const int n0 = blockIdx.y * BN;

    const int brow = tid >> 5;
    const int bc4  = tid & 31;

    ull acc[TM][TN2];
#pragma unroll
    for (int i = 0; i < TM; i++)
#pragma unroll
        for (int j = 0; j < TN2; j++) acc[i][j] = 0ULL;

    float4 aR[ALD], bR0, bR1;

    auto ldg = [&](int kt) {
#pragma unroll
        for (int i = 0; i < ALD; i++) {
            const int idx = tid + i * 256;
            const int r = idx >> 2, c4 = idx & 3;
            const int gr = m0 + r;
            aR[i] = (gr < M)
                ? *reinterpret_cast<const float4*>(Ag + (size_t)gr * K + kt * BK + c4 * 4)
                : make_float4(0.f, 0.f, 0.f, 0.f);
        }
        bR0 = *reinterpret_cast<const float4*>(Bg + (size_t)(kt * BK + brow)     * N + n0 + bc4 * 4);
        bR1 = *reinterpret_cast<const float4*>(Bg + (size_t)(kt * BK + brow + 8) * N + n0 + bc4 * 4);
    };
    auto sts = [&](int buf) {
#pragma unroll
        for (int i = 0; i < ALD; i++) {
            const int idx = tid + i * 256;
            const int r = idx >> 2, c4 = idx & 3;
            *reinterpret_cast<float2*>(&As2[buf][c4 * 4 + 0][2 * r]) = make_float2(aR[i].x, aR[i].x);
            *reinterpret_cast<float2*>(&As2[buf][c4 * 4 + 1][2 * r]) = make_float2(aR[i].y, aR[i].y);
            *reinterpret_cast<float2*>(&As2[buf][c4 * 4 + 2][2 * r]) = make_float2(aR[i].z, aR[i].z);
            *reinterpret_cast<float2*>(&As2[buf][c4 * 4 + 3][2 * r]) = make_float2(aR[i].w, aR[i].w);
        }
        *reinterpret_cast<float4*>(&Bs[buf][brow][bc4 * 4])     = bR0;
        *reinterpret_cast<float4*>(&Bs[buf][brow + 8][bc4 * 4]) = bR1;
    };

    ldg(0); sts(0); __syncthreads();

    const int nt = K >> 4;
    for (int t = 0; t < nt; t++) {
        const int buf = t & 1;
        if (t + 1 < nt) ldg(t + 1);           // prefetch, hidden under compute

#pragma unroll
        for (int k = 0; k < BK; k++) {
            ull a[TM];
            const ulonglong2* ap =
                reinterpret_cast<const ulonglong2*>(&As2[buf][k][ty * 2 * TM]);
#pragma unroll
            for (int q = 0; q < TM / 2; q++) {
                ulonglong2 v = ap[q];
                a[2 * q] = v.x; a[2 * q + 1] = v.y;
            }
            ull b[TN2];
            ulonglong2 b0 = *reinterpret_cast<const ulonglong2*>(&Bs[buf][k][tx * 4]);
            ulonglong2 b1 = *reinterpret_cast<const ulonglong2*>(&Bs[buf][k][64 + tx * 4]);
            b[0] = b0.x; b[1] = b0.y; b[2] = b1.x; b[3] = b1.y;
#pragma unroll
            for (int i = 0; i < TM; i++)
#pragma unroll
                for (int j = 0; j < TN2; j++)
                    asm("fma.rn.f32x2 %0, %1, %2, %0;"
                        : "+l"(acc[i][j]) : "l"(a[i]), "l"(b[j]));
        }

        if (t + 1 < nt) sts(buf ^ 1);
        __syncthreads();
    }

    // --- epilogue ----------------------------------------------------------
    float bv[8];
#pragma unroll
    for (int j = 0; j < 4; j++) {
        bv[j]     = bias ? bias[n0 + tx * 4 + j]      : 0.f;
        bv[4 + j] = bias ? bias[n0 + 64 + tx * 4 + j] : 0.f;
    }

#pragma unroll
    for (int i = 0; i < TM; i++) {
        const int r = m0 + ty * TM + i;
        if (r < M) {
            const float rs = rowscale ? rowscale[r] : 1.f;
            float w[8];
#pragma unroll
            for (int j = 0; j < 4; j++) {
                unsigned lo, hi;
                asm("mov.b64 {%0,%1}, %2;" : "=r"(lo), "=r"(hi) : "l"(acc[i][j]));
                w[2 * j]     = __uint_as_float(lo) + bv[2 * j]     * rs;
                w[2 * j + 1] = __uint_as_float(hi) + bv[2 * j + 1] * rs;
            }
            float* c0 = C + (size_t)r * N + n0 + tx * 4;
            float* c1 = c0 + 64;
            if (EPI >= 2) {
                float4 p0 = *reinterpret_cast<float4*>(c0);
                float4 p1 = *reinterpret_cast<float4*>(c1);
                w[0] += p0.x; w[1] += p0.y; w[2] += p0.z; w[3] += p0.w;
                w[4] += p1.x; w[5] += p1.y; w[6] += p1.z; w[7] += p1.w;
            }
            if (EPI == 3) {
#pragma unroll
                for (int j = 0; j < 8; j++) w[j] = fmaxf(w[j], 0.f);
            }
            *reinterpret_cast<float4*>(c0) = make_float4(w[0], w[1], w[2], w[3]);
            *reinterpret_cast<float4*>(c1) = make_float4(w[4], w[5], w[6], w[7]);
        }
    }
}

// ---------------------------------------------------------------------------
// Elementwise / graph kernels (both branches fused)
// ---------------------------------------------------------------------------
__global__ void zero_kernel(float4* __restrict__ p, int n4) {
    int i = blockIdx.x * blockDim.x + threadIdx.x;
    if (i < n4) p[i] = make_float4(0.f, 0.f, 0.f, 0.f);
}

__global__ void deg_kernel(const int* __restrict__ ei1, const int* __restrict__ ei2,
                           float* __restrict__ deg) {
    int e = blockIdx.x * blockDim.x + threadIdx.x;
    if (e >= 2 * NE) return;
    int t = (e < NE) ? ei1[e] : (ei2[e - NE] + NN);
    atomicAdd(deg + t, 1.0f);
}

// Per edge: t = relu(A[src] + B[tgt]) (256 floats) ; T[tgt] += t.
// 64 threads per edge (one float4 each). Both branches in one grid.
__global__ void edge_kernel(const int* __restrict__ ei1, const int* __restrict__ ei2,
                            const float* __restrict__ A, const float* __restrict__ B,
                            float* __restrict__ T) {
    long long gid = (long long)blockIdx.x * blockDim.x + threadIdx.x;
    int e    = (int)(gid >> 6);
    int lane = (int)(gid & 63);
    if (e >= 2 * NE) return;
    int tgt, src;
    if (e < NE) { tgt = ei1[e];      src = ei1[NE + e]; }
    else        { e -= NE; tgt = ei2[e] + NN; src = ei2[NE + e] + NN; }
    float4 a = *(reinterpret_cast<const float4*>(A + (size_t)src * 256) + lane);
    float4 b = *(reinterpret_cast<const float4*>(B + (size_t)tgt * 256) + lane);
    float4 t;
    t.x = fmaxf(a.x + b.x, 0.f);
    t.y = fmaxf(a.y + b.y, 0.f);
    t.z = fmaxf(a.z + b.z, 0.f);
    t.w = fmaxf(a.w + b.w, 0.f);
    atomicAdd(reinterpret_cast<float4*>(T + (size_t)tgt * 256) + lane, t);
}

// v = sigmoid(nx[:, :128]) * nx[:, 128:] ; gg[graph(node)] += v
__global__ void gatepool_kernel(const float* __restrict__ nx,
                                const int* __restrict__ batch1,
                                const int* __restrict__ batch2,
                                float* __restrict__ gg) {
    int i = blockIdx.x * blockDim.x + threadIdx.x;
    if (i >= NB * 32) return;
    int node = i >> 5;
    int c4   = i & 31;
    const float4* row = reinterpret_cast<const float4*>(nx + (size_t)node * 256);
    float4 g = row[c4];
    float4 v = row[32 + c4];
    float4 o;
    o.x = v.x / (1.f + expf(-g.x));
    o.y = v.y / (1.f + expf(-g.y));
    o.z = v.z / (1.f + expf(-g.z));
    o.w = v.w / (1.f + expf(-g.w));
    int b = (node < NN) ? batch1[node] : (batch2[node - NN] + NG);
    atomicAdd(reinterpret_cast<float4*>(gg + (size_t)b * HD) + c4, o);
}

// ---------------------------------------------------------------------------
// Host orchestration — both branches stacked (M = 20000 GEMMs, shared weights)
// ---------------------------------------------------------------------------
extern "C" void kernel_launch(void* const* d_in, const int* in_sizes, int n_in,
                              void* d_out, int out_size)
{
    (void)in_sizes; (void)n_in; (void)out_size;

    const float* x1      = (const float*)d_in[0];
    const int*   ei1     = (const int*)  d_in[1];
    const int*   batch1  = (const int*)  d_in[2];
    const float* x2      = (const float*)d_in[3];
    const int*   ei2     = (const int*)  d_in[4];
    const int*   batch2  = (const int*)  d_in[5];
    const float* W_emb   = (const float*)d_in[6];
    const float* b_emb   = (const float*)d_in[7];
    const float* msg_W1  = (const float*)d_in[8];
    const float* msg_b1  = (const float*)d_in[9];
    const float* msg_W2  = (const float*)d_in[10];
    const float* msg_b2  = (const float*)d_in[11];
    const float* upd_W1  = (const float*)d_in[12];
    const float* upd_b1  = (const float*)d_in[13];
    const float* upd_W2  = (const float*)d_in[14];
    const float* upd_b2  = (const float*)d_in[15];
    const float* node_W  = (const float*)d_in[16];
    const float* node_b  = (const float*)d_in[17];
    const float* graph_W = (const float*)d_in[18];
    const float* graph_b = (const float*)d_in[19];

    void *ph, *pA, *pB, *pT, *pdg, *pgg;
    cudaGetSymbolAddress(&ph,  g_h);
    cudaGetSymbolAddress(&pA,  g_A);
    cudaGetSymbolAddress(&pB,  g_B);
    cudaGetSymbolAddress(&pT,  g_T);
    cudaGetSymbolAddress(&pdg, g_dg);
    cudaGetSymbolAddress(&pgg, g_gg);
    float* h  = (float*)ph;
    float* A  = (float*)pA;
    float* B  = (float*)pB;
    float* T  = (float*)pT;
    float* dg = (float*)pdg;
    float* gg = (float*)pgg;

    const dim3 gBig ((NB + 127) / 128, 2);   // BM=128, N=256 -> 314 blocks
    const dim3 gMed ((NB + 63) / 64, 1);     // BM=64,  N=128 -> 313 blocks
    const dim3 gEmb ((NN + 63) / 64, 1);     // per-branch embedding

    // h = x @ W_emb + b_emb  (two source buffers, stacked destination)
    sgemm<0, 4><<<gEmb, 256>>>(x1, W_emb, h,            b_emb, nullptr, NN, HD, 64);
    sgemm<0, 4><<<gEmb, 256>>>(x2, W_emb, h + (size_t)NN * HD, b_emb, nullptr, NN, HD, 64);

    // per-node in-degree (both branches)
    zero_kernel<<<(NB / 4 + 255) / 256, 256>>>((float4*)dg, NB / 4);
    deg_kernel<<<(2 * NE + 255) / 256, 256>>>(ei1, ei2, dg);

    for (int l = 0; l < 2; l++) {
        const float* Wm1 = msg_W1 + (size_t)l * 256 * 256;
        const float* bm1 = msg_b1 + (size_t)l * 256;
        const float* Wm2 = msg_W2 + (size_t)l * 256 * 256;
        const float* bm2 = msg_b2 + (size_t)l * 256;
        const float* Wu1 = upd_W1 + (size_t)l * 384 * 256;
        const float* bu1 = upd_b1 + (size_t)l * 256;
        const float* Wu2 = upd_W2 + (size_t)l * 256 * 128;
        const float* bu2 = upd_b2 + (size_t)l * 128;

        // A = h @ W1[:128,:] + b1 ; B = h @ W1[128:,:]   (node-level hoist)
        sgemm<0, 8><<<gBig, 256>>>(h, Wm1,             A, bm1,     nullptr, NB, 256, 128);
        sgemm<0, 8><<<gBig, 256>>>(h, Wm1 + 128 * 256, B, nullptr, nullptr, NB, 256, 128);

        // T[n] = sum_{e: tgt=n} relu(A[src] + B[tgt])
        zero_kernel<<<(NB * 64 + 255) / 256, 256>>>((float4*)T, NB * 64);
        edge_kernel<<<(2 * NE * 64 + 255) / 256, 256>>>(ei1, ei2, A, B, T);

        // agg = T @ W2 + deg * b2   (hoist past segment-sum) -> A
        sgemm<0, 8><<<gBig, 256>>>(T, Wm2, A, bm2, dg, NB, 256, 256);

        // u1 = relu(agg @ Wu1[:256] + h @ Wu1[256:] + bu1)   (concat fused away)
        sgemm<0, 8><<<gBig, 256>>>(A, Wu1,             B, bu1,     nullptr, NB, 256, 256);
        sgemm<3, 8><<<gBig, 256>>>(h, Wu1 + 256 * 256, B, nullptr, nullptr, NB, 256, 128);

        // h += u1 @ uW2 + ub2       (residual epilogue)
        sgemm<2, 4><<<gMed, 256>>>(B, Wu2, h, bu2, nullptr, NB, 128, 256);
    }

    // readout: nx = h @ node_W + node_b -> T ; gate+pool ; graph GEMM
    sgemm<0, 8><<<gBig, 256>>>(h, node_W, T, node_b, nullptr, NB, 256, 128);
    zero_kernel<<<(2 * NG * 32 + 255) / 256, 256>>>((float4*)gg, 2 * NG * 32);
    gatepool_kernel<<<(NB * 32 + 255) / 256, 256>>>(T, batch1, batch2, gg);
    // out[2,32,128] contiguous = [64,128]
    sgemm<0, 4><<<dim3(1, 1), 256>>>(gg, graph_W, (float*)d_out, graph_b, nullptr,
                                     2 * NG, HD, HD);
}